// round 13
// baseline (speedup 1.0000x reference)
#include <cuda_runtime.h>
#include <math.h>

#define NB 32
#define NH 512
#define NW 512
#define NM 96
#define NCo 263
#define SW 264
#define RANKSEL 105334u   // 0-based median rank incl. 1581 pad zeros per plane
#define CAP 207872

#define T0   0.05441584224308161f
#define T1   0.3128715909144659f
#define T2   0.6756307362980128f
#define T3   0.5853546836548691f
#define T4  -0.015829105256023893f
#define T5  -0.2840155429624281f
#define T6   0.00047248457399797254f
#define T7   0.128747426620186f
#define T8  -0.01736930100202211f
#define T9  -0.04408825393106472f
#define T10  0.013981027917015516f
#define T11  0.008746094047015655f
#define T12 -0.00487035299301066f
#define T13 -0.0003917403729959771f
#define T14  0.0006754494059985568f
#define T15 -0.00011747678400228192f

__constant__ __align__(8) float RLB[16][2] = {
 {T0,T0},{T1,T1},{T2,T2},{T3,T3},{T4,T4},{T5,T5},{T6,T6},{T7,T7},
 {T8,T8},{T9,T9},{T10,T10},{T11,T11},{T12,T12},{T13,T13},{T14,T14},{T15,T15}};
__constant__ __align__(8) float DHB[16][2] = {
 {T15,T15},{-T14,-T14},{T13,T13},{-T12,-T12},{T11,T11},{-T10,-T10},{T9,T9},{-T8,-T8},
 {T7,T7},{-T6,-T6},{T5,T5},{-T4,-T4},{T3,T3},{-T2,-T2},{T1,T1},{-T0,-T0}};
__constant__ __align__(8) float RLNB[16][2] = {
 {-T0,-T0},{-T1,-T1},{-T2,-T2},{-T3,-T3},{-T4,-T4},{-T5,-T5},{-T6,-T6},{-T7,-T7},
 {-T8,-T8},{-T9,-T9},{-T10,-T10},{-T11,-T11},{-T12,-T12},{-T13,-T13},{-T14,-T14},{-T15,-T15}};

typedef unsigned long long u64;
__device__ __forceinline__ u64 pk2(float lo, float hi) {
  u64 r; asm("mov.b64 %0, {%1, %2};" : "=l"(r) : "f"(lo), "f"(hi)); return r;
}
__device__ __forceinline__ u64 ffma2(u64 a, u64 b, u64 c) {
  u64 d; asm("fma.rn.f32x2 %0, %1, %2, %3;" : "=l"(d) : "l"(a), "l"(b), "l"(c)); return d;
}
__device__ __forceinline__ float2 up2(u64 v) {
  float2 f; asm("mov.b64 {%0, %1}, %2;" : "=f"(f.x), "=f"(f.y) : "l"(v)); return f;
}
__device__ __forceinline__ u64 cpair(const float (*tab)[2], int i) {
  return *(const u64*)(tab[i]);
}

__device__ __forceinline__ void fwd8(const float* samp, float* a, float* d) {
  u64 p[18];
  #pragma unroll
  for (int j = 0; j < 18; j++) p[j] = pk2(samp[j], samp[j+4]);
  u64 aP = 0ull, aQ = 0ull, dP = 0ull, dQ = 0ull;
  #pragma unroll
  for (int i = 0; i < 16; i++) {
    u64 rl = cpair(RLB, i), dh = cpair(DHB, i);
    aP = ffma2(rl, p[i],   aP);
    aQ = ffma2(rl, p[i+2], aQ);
    dP = ffma2(dh, p[i],   dP);
    dQ = ffma2(dh, p[i+2], dQ);
  }
  float2 f;
  f = up2(aP); a[0] = f.x; a[2] = f.y;
  f = up2(aQ); a[1] = f.x; a[3] = f.y;
  f = up2(dP); d[0] = f.x; d[2] = f.y;
  f = up2(dQ); d[1] = f.x; d[3] = f.y;
}

__device__ __forceinline__ void inv8(const float* ac, const float* dc,
                                     float* y0, float* y1) {
  u64 pa[9], pd[9];
  #pragma unroll
  for (int j = 0; j < 9; j++) { pa[j] = pk2(ac[j], ac[j+2]); pd[j] = pk2(dc[j], dc[j+2]); }
  u64 y0P = 0ull, y0Q = 0ull, y1P = 0ull, y1Q = 0ull;
  #pragma unroll
  for (int u = 0; u < 8; u++) {
    u64 a1 = pa[7-u], a2 = pa[8-u], d1 = pd[7-u], d2 = pd[8-u];
    u64 re = cpair(RLB, 2*u), rh = cpair(RLB, 15-2*u);
    u64 ro = cpair(RLB, 2*u+1), rn = cpair(RLNB, 14-2*u);
    y0P = ffma2(a1, re, y0P); y0P = ffma2(d1, rh, y0P);
    y0Q = ffma2(a2, re, y0Q); y0Q = ffma2(d2, rh, y0Q);
    y1P = ffma2(a1, ro, y1P); y1P = ffma2(d1, rn, y1P);
    y1Q = ffma2(a2, ro, y1Q); y1Q = ffma2(d2, rn, y1Q);
  }
  float2 f;
  f = up2(y0P); y0[0] = f.x; y0[2] = f.y;
  f = up2(y0Q); y0[1] = f.x; y0[3] = f.y;
  f = up2(y1P); y1[0] = f.x; y1[2] = f.y;
  f = up2(y1Q); y1[1] = f.x; y1[3] = f.y;
}

__device__ float g_lo[(size_t)NM*NH*SW];
__device__ float g_hi[(size_t)NM*NH*SW];
__device__ float g_ll[(size_t)NM*SW*SW];   // subbands: layout [m][jh][w]
__device__ float g_lh[(size_t)NM*SW*SW];
__device__ float g_hl[(size_t)NM*SW*SW];
__device__ float g_hh[(size_t)NM*SW*SW];
__device__ float g_thr[NM];
__device__ unsigned g_hist0[NM*2048];
__device__ unsigned g_hist1[NM*2048];
__device__ unsigned g_ccnt[NM];
__device__ unsigned g_pref0[NM];
__device__ unsigned g_rank1[NM];
__device__ unsigned g_cand[(size_t)NM*CAP];

__device__ __forceinline__ int refl(int q, int n) {
  q = (q < 0) ? (-q - 1) : q;
  return (q >= n) ? (2*n - 1 - q) : q;
}
__device__ __forceinline__ float softf(float c, float t) {
  float a = fabsf(c) - t;
  return (a > 0.f) ? copysignf(a, c) : 0.f;
}
__device__ __forceinline__ void hadd(unsigned* h, unsigned bin) {
  unsigned mk = __match_any_sync(__activemask(), bin);
  int lane = threadIdx.x & 31;
  if ((__ffs(mk) - 1) == lane) atomicAdd(&h[bin], (unsigned)__popc(mk));
}

template<int NT, int K>
__device__ void select_bin(const unsigned* hist, unsigned rank,
                           unsigned* s_bin, unsigned* s_rem) {
  __shared__ unsigned wtot[NT/32];
  int tid = threadIdx.x, lane = tid & 31, wid = tid >> 5;
  unsigned tsum = 0;
  #pragma unroll
  for (int k = 0; k < K; k++) tsum += hist[tid*K + k];
  unsigned v = tsum;
  #pragma unroll
  for (int o = 1; o < 32; o <<= 1) {
    unsigned n = __shfl_up_sync(0xffffffffu, v, o);
    if (lane >= o) v += n;
  }
  if (lane == 31) wtot[wid] = v;
  __syncthreads();
  if (tid == 0) {
    unsigned s = 0;
    for (int w = 0; w < NT/32; w++) { unsigned t = wtot[w]; wtot[w] = s; s += t; }
  }
  __syncthreads();
  unsigned incl = v + wtot[wid];
  unsigned excl = incl - tsum;
  if (rank >= excl && rank < incl) {
    unsigned c = excl;
    #pragma unroll
    for (int k = 0; k < K; k++) {
      unsigned hb = hist[tid*K + k];
      if (rank < c + hb) { *s_bin = (unsigned)(tid*K + k); *s_rem = rank - c; break; }
      c += hb;
    }
  }
  __syncthreads();
}

// ---- tiny zero kernels (split so k_fwd_cols is the 4th launch -> profiled) --
__global__ void k_zero_a() {
  int i = blockIdx.x*256 + threadIdx.x;
  if (i < NM*2048) g_hist0[i] = 0u;
  if (i < NM) g_ccnt[i] = 0u;
}
__global__ void k_zero_b() {
  int i = blockIdx.x*256 + threadIdx.x;
  if (i < NM*2048) g_hist1[i] = 0u;
}

// ---- A: row DWT (along W), 2 rows/block, 3 channels ------------------------
__global__ void __launch_bounds__(256) k_fwd_rows(const float* __restrict__ x) {
  __shared__ float s[2][1728];
  int h0 = blockIdx.x*2, b = blockIdx.y;
  const float4* row4 = (const float4*)(x + (size_t)(b*NH + h0)*NW*3);
  #pragma unroll
  for (int u = 0; u < 3; u++) {
    int i = u*256 + threadIdx.x;
    float4 v = row4[i];
    int rr = i / 384, lin = 4*(i - 384*rr);
    #pragma unroll
    for (int e = 0; e < 4; e++) {
      int l = lin + e, c = l % 3, w = l / 3;
      s[rr][c*576 + w + (w >> 3)] = (&v.x)[e];
    }
  }
  __syncthreads();
  for (int t = threadIdx.x; t < 396; t += 256) {
    int rr = t / 198, t2 = t - 198*rr;
    int c = t2 / 66, g = t2 - 66*c;
    const float* sc = s[rr] + c*576;
    float samp[22];
    int q0 = 8*g - 14;
    #pragma unroll
    for (int k = 0; k < 22; k++) { int q = refl(q0 + k, NW); samp[k] = sc[q + (q >> 3)]; }
    float a[4], d[4];
    fwd8(samp, a, d);
    size_t base = ((size_t)(b*3 + c)*NH + h0 + rr)*SW + 4*g;
    *(float4*)(g_lo + base) = make_float4(a[0],a[1],a[2],a[3]);
    *(float4*)(g_hi + base) = make_float4(d[0],d[1],d[2],d[3]);
  }
}

// ---- B: column DWT split-H -> subbands [m][jh][w] + fused pass-0 hist ------
__global__ void __launch_bounds__(256) k_fwd_cols() {
  __shared__ float s2[32*151];
  __shared__ unsigned hist[2048];
  int bx = blockIdx.x, wt = bx % 9, jc = bx / 9;
  int m = blockIdx.y, z = blockIdx.z;
  int w0 = wt*32, g0 = 17*jc;
  int ge = min(g0 + 16, 65);
  int lo_q = 8*g0 - 14;
  int nrows = 8*(ge - g0) + 22;
  const float* in = (z ? g_hi : g_lo) + (size_t)m*NH*SW;
  float* outA = (z ? g_hl : g_ll) + (size_t)m*SW*SW;
  float* outD = (z ? g_hh : g_lh) + (size_t)m*SW*SW;
  for (int i = threadIdx.x; i < 2048; i += 256) hist[i] = 0u;
  // unrolled load: 19 independent predicated LDGs per thread (MLP)
  {
    int nelem = 32*nrows;
    #pragma unroll
    for (int u = 0; u < 19; u++) {
      int idx = u*256 + threadIdx.x;
      if (idx < nelem) {
        int wl = idx & 31, rr = idx >> 5, w = w0 + wl;
        int q = refl(lo_q + rr, NH);
        s2[wl*151 + rr] = (w < NCo) ? in[(size_t)q*SW + w] : 0.f;
      }
    }
  }
  __syncthreads();
  int lane = threadIdx.x & 31, warp = threadIdx.x >> 5;
  int w = w0 + lane;
  const float* col = s2 + lane*151;
  for (int g = g0 + warp; g <= ge; g += 8) {
    int off = 8*(g - g0);
    float samp[22];
    #pragma unroll
    for (int k = 0; k < 22; k++) samp[k] = col[off + k];
    float a[4], d[4];
    fwd8(samp, a, d);
    if (g == 65) { a[3] = 0.f; d[3] = 0.f; } // jh==263 pad row
    if (w < SW) {
      #pragma unroll
      for (int r = 0; r < 4; r++) {
        int jh = 4*g + r;
        outA[(size_t)jh*SW + w] = a[r];
        outD[(size_t)jh*SW + w] = d[r];
        hadd(hist, __float_as_uint(fabsf(d[r])) >> 21);
        if (z) hadd(hist, __float_as_uint(fabsf(a[r])) >> 21);
      }
    }
  }
  __syncthreads();
  for (int i = threadIdx.x; i < 2048; i += 256)
    if (hist[i]) atomicAdd(&g_hist0[m*2048 + i], hist[i]);
}

// ---- M2: redundant pass-0 select + refine hist + compact matching keys -----
__global__ void __launch_bounds__(256) k_pass1() {
  __shared__ unsigned hist[2048];
  __shared__ unsigned s_bin, s_rem;
  int cx = blockIdx.x, m = blockIdx.y, band = blockIdx.z;
  select_bin<256, 8>(g_hist0 + m*2048, RANKSEL, &s_bin, &s_rem);
  unsigned pref0 = s_bin;
  if (cx == 0 && band == 0 && threadIdx.x == 0) {
    g_pref0[m] = s_bin; g_rank1[m] = s_rem;
  }
  const float* bp = (band == 0 ? g_lh : (band == 1 ? g_hl : g_hh)) + (size_t)m*SW*SW;
  const float4* p = (const float4*)bp;
  for (int i = threadIdx.x; i < 2048; i += 256) hist[i] = 0u;
  __syncthreads();
  int lo = cx*2178, hi = lo + 2178;
  int lane = threadIdx.x & 31;
  for (int base = lo; base < hi; base += 256) {
    int i = base + threadIdx.x;
    float4 v = make_float4(0.f, 0.f, 0.f, 0.f);
    if (i < hi) v = p[i];
    #pragma unroll
    for (int e = 0; e < 4; e++) {
      unsigned key = __float_as_uint(fabsf((&v.x)[e]));
      bool ok = (i < hi) && ((key >> 21) == pref0);
      unsigned mk = __ballot_sync(0xffffffffu, ok);
      if (mk) {
        int leader = __ffs(mk) - 1;
        unsigned basec = 0;
        if (lane == leader) basec = atomicAdd(&g_ccnt[m], (unsigned)__popc(mk));
        basec = __shfl_sync(0xffffffffu, basec, leader);
        if (ok) {
          atomicAdd(&hist[(key >> 10) & 2047u], 1u);
          g_cand[(size_t)m*CAP + basec + __popc(mk & ((1u << lane) - 1u))] = key;
        }
      }
    }
  }
  __syncthreads();
  for (int i = threadIdx.x; i < 2048; i += 256)
    if (hist[i]) atomicAdd(&g_hist1[m*2048 + i], hist[i]);
}

// ---- M3: finish on candidates -> threshold ---------------------------------
__global__ void __launch_bounds__(512) k_final() {
  int m = blockIdx.x;
  __shared__ unsigned sh[2048];
  __shared__ unsigned s_bin, s_rem;
  for (int i = threadIdx.x; i < 2048; i += 512) sh[i] = g_hist1[m*2048 + i];
  __syncthreads();
  select_bin<512, 4>(sh, g_rank1[m], &s_bin, &s_rem);
  unsigned pref01 = (g_pref0[m] << 11) | s_bin;
  unsigned r2 = s_rem;
  __syncthreads();
  for (int i = threadIdx.x; i < 1024; i += 512) sh[i] = 0u;
  __syncthreads();
  unsigned cnt = g_ccnt[m];
  const unsigned* cand = g_cand + (size_t)m*CAP;
  for (unsigned i = threadIdx.x; i < cnt; i += 512) {
    unsigned key = cand[i];
    if ((key >> 10) == pref01) atomicAdd(&sh[key & 1023u], 1u);
  }
  __syncthreads();
  select_bin<512, 2>(sh, r2, &s_bin, &s_rem);
  if (threadIdx.x == 0) {
    unsigned key = (pref01 << 10) | s_bin;
    double med = (double)__uint_as_float(key);
    g_thr[m] = (float)(med / 0.6745 * sqrt(2.0 * log(262144.0)));
  }
}

// ---- C: inverse column DWT (subbands [jh][w]), soft fused ------------------
__global__ void __launch_bounds__(256) k_inv_cols() {
  __shared__ float ca[32*71], cd[32*71];
  int bx = blockIdx.x, wt = bx % 9, jc = bx / 9;
  int m = blockIdx.y, z = blockIdx.z;
  int w0 = wt*32, gc0 = 16*jc, p_lo = 64*jc;
  const float* A = (z ? g_hl : g_ll) + (size_t)m*SW*SW;
  const float* D = (z ? g_hh : g_lh) + (size_t)m*SW*SW;
  float* out = (z ? g_hi : g_lo) + (size_t)m*NH*SW;
  float thr = g_thr[m];
  // unrolled load: 9 independent predicated LDG pairs per thread (MLP)
  #pragma unroll
  for (int u = 0; u < 9; u++) {
    int idx = u*256 + threadIdx.x;
    if (idx < 32*71) {
      int wl = idx & 31, rr = idx >> 5;
      int w = w0 + wl, p = p_lo + rr;
      float va = 0.f, vd = 0.f;
      if (w < NCo) { va = A[(size_t)p*SW + w]; vd = D[(size_t)p*SW + w]; }
      if (z) va = softf(va, thr);
      vd = softf(vd, thr);
      ca[wl*71 + rr] = va;
      cd[wl*71 + rr] = vd;
    }
  }
  __syncthreads();
  int lane = threadIdx.x & 31, warp = threadIdx.x >> 5;
  int w = w0 + lane;
  bool wok = (w < NCo);
  const float* cap = ca + lane*71;
  const float* cdp = cd + lane*71;
  for (int gl = warp; gl < 16; gl += 8) {
    int gc = gc0 + gl, pr = 4*gl;
    float ac[11], dc[11];
    #pragma unroll
    for (int k = 0; k < 11; k++) { ac[k] = cap[pr + k]; dc[k] = cdp[pr + k]; }
    float y0[4], y1[4];
    inv8(ac, dc, y0, y1);
    if (wok) {
      #pragma unroll
      for (int r = 0; r < 4; r++) {
        int i0 = 8*gc + 2*r;
        out[(size_t)i0*SW + w]     = y0[r];
        out[(size_t)(i0+1)*SW + w] = y1[r];
      }
    }
  }
}

// ---- D: inverse row DWT + NHWC interleave, 2 rows/block --------------------
__global__ void __launch_bounds__(256) k_inv_rows(float* __restrict__ out) {
  __shared__ float ca[2][888], cd[2][888], rowbuf[2][1536];
  int h0 = blockIdx.x*2, b = blockIdx.y;
  #pragma unroll
  for (int u = 0; u < 2; u++) {
    int i = u*256 + threadIdx.x;
    if (i < 396) {
      int rr = i / 198, t2 = i - 198*rr;
      int c = t2 / 66, f = t2 - 66*c;
      const float4* rl4 = (const float4*)(g_lo + ((size_t)(b*3 + c)*NH + h0 + rr)*SW);
      const float4* rh4 = (const float4*)(g_hi + ((size_t)(b*3 + c)*NH + h0 + rr)*SW);
      float4 va = rl4[f], vd = rh4[f];
      int a0 = c*296 + 4*f + (f >> 1);
      #pragma unroll
      for (int e = 0; e < 4; e++) { ca[rr][a0 + e] = (&va.x)[e]; cd[rr][a0 + e] = (&vd.x)[e]; }
    }
  }
  __syncthreads();
  for (int t = threadIdx.x; t < 384; t += 256) {
    int rr = t / 192, rem = t - 192*rr;
    int c = rem >> 6, gc = rem & 63, p0 = 4*gc;
    float ac[11], dc[11];
    #pragma unroll
    for (int k = 0; k < 11; k++) {
      int p = p0 + k, a = c*296 + p + (p >> 3);
      ac[k] = ca[rr][a]; dc[k] = cd[rr][a];
    }
    float y0[4], y1[4];
    inv8(ac, dc, y0, y1);
    #pragma unroll
    for (int r = 0; r < 4; r++) {
      int o = 2*(p0 + r);
      rowbuf[rr][o*3 + c]       = y0[r];
      rowbuf[rr][(o + 1)*3 + c] = y1[r];
    }
  }
  __syncthreads();
  float4* orow = (float4*)(out + (size_t)(b*NH + h0)*NW*3);
  const float4* rb = (const float4*)rowbuf;
  #pragma unroll
  for (int u = 0; u < 3; u++) orow[u*256 + threadIdx.x] = rb[u*256 + threadIdx.x];
}

extern "C" void kernel_launch(void* const* d_in, const int* in_sizes, int n_in,
                              void* d_out, int out_size) {
  const float* x = (const float*)d_in[0];
  float* out = (float*)d_out;
  k_zero_a<<<(NM*2048 + 255)/256, 256>>>();
  k_zero_b<<<(NM*2048 + 255)/256, 256>>>();
  k_fwd_rows<<<dim3(NH/2, NB), 256>>>(x);
  k_fwd_cols<<<dim3(36, NM, 2), 256>>>();   // 4th launch -> ncu captures this
  k_pass1<<<dim3(8, NM, 3), 256>>>();
  k_final<<<NM, 512>>>();
  k_inv_cols<<<dim3(36, NM, 2), 256>>>();
  k_inv_rows<<<dim3(NH/2, NB), 256>>>(out);
}

// round 14
// speedup vs baseline: 1.0662x; 1.0662x over previous
#include <cuda_runtime.h>
#include <math.h>

#define NB 32
#define NH 512
#define NW 512
#define NM 96
#define NCo 263
#define SW 264
#define RANKSEL 105334u   // 0-based median rank incl. 1581 pad zeros per plane
#define CAP 207872

#define T0   0.05441584224308161f
#define T1   0.3128715909144659f
#define T2   0.6756307362980128f
#define T3   0.5853546836548691f
#define T4  -0.015829105256023893f
#define T5  -0.2840155429624281f
#define T6   0.00047248457399797254f
#define T7   0.128747426620186f
#define T8  -0.01736930100202211f
#define T9  -0.04408825393106472f
#define T10  0.013981027917015516f
#define T11  0.008746094047015655f
#define T12 -0.00487035299301066f
#define T13 -0.0003917403729959771f
#define T14  0.0006754494059985568f
#define T15 -0.00011747678400228192f

__constant__ __align__(8) float RLB[16][2] = {
 {T0,T0},{T1,T1},{T2,T2},{T3,T3},{T4,T4},{T5,T5},{T6,T6},{T7,T7},
 {T8,T8},{T9,T9},{T10,T10},{T11,T11},{T12,T12},{T13,T13},{T14,T14},{T15,T15}};
__constant__ __align__(8) float DHB[16][2] = {
 {T15,T15},{-T14,-T14},{T13,T13},{-T12,-T12},{T11,T11},{-T10,-T10},{T9,T9},{-T8,-T8},
 {T7,T7},{-T6,-T6},{T5,T5},{-T4,-T4},{T3,T3},{-T2,-T2},{T1,T1},{-T0,-T0}};
__constant__ __align__(8) float RLNB[16][2] = {
 {-T0,-T0},{-T1,-T1},{-T2,-T2},{-T3,-T3},{-T4,-T4},{-T5,-T5},{-T6,-T6},{-T7,-T7},
 {-T8,-T8},{-T9,-T9},{-T10,-T10},{-T11,-T11},{-T12,-T12},{-T13,-T13},{-T14,-T14},{-T15,-T15}};

typedef unsigned long long u64;
__device__ __forceinline__ u64 pk2(float lo, float hi) {
  u64 r; asm("mov.b64 %0, {%1, %2};" : "=l"(r) : "f"(lo), "f"(hi)); return r;
}
__device__ __forceinline__ u64 ffma2(u64 a, u64 b, u64 c) {
  u64 d; asm("fma.rn.f32x2 %0, %1, %2, %3;" : "=l"(d) : "l"(a), "l"(b), "l"(c)); return d;
}
__device__ __forceinline__ float2 up2(u64 v) {
  float2 f; asm("mov.b64 {%0, %1}, %2;" : "=f"(f.x), "=f"(f.y) : "l"(v)); return f;
}
__device__ __forceinline__ u64 cpair(const float (*tab)[2], int i) {
  return *(const u64*)(tab[i]);
}

__device__ __forceinline__ void fwd8(const float* samp, float* a, float* d) {
  u64 p[18];
  #pragma unroll
  for (int j = 0; j < 18; j++) p[j] = pk2(samp[j], samp[j+4]);
  u64 aP = 0ull, aQ = 0ull, dP = 0ull, dQ = 0ull;
  #pragma unroll
  for (int i = 0; i < 16; i++) {
    u64 rl = cpair(RLB, i), dh = cpair(DHB, i);
    aP = ffma2(rl, p[i],   aP);
    aQ = ffma2(rl, p[i+2], aQ);
    dP = ffma2(dh, p[i],   dP);
    dQ = ffma2(dh, p[i+2], dQ);
  }
  float2 f;
  f = up2(aP); a[0] = f.x; a[2] = f.y;
  f = up2(aQ); a[1] = f.x; a[3] = f.y;
  f = up2(dP); d[0] = f.x; d[2] = f.y;
  f = up2(dQ); d[1] = f.x; d[3] = f.y;
}

__device__ __forceinline__ void inv8(const float* ac, const float* dc,
                                     float* y0, float* y1) {
  u64 pa[9], pd[9];
  #pragma unroll
  for (int j = 0; j < 9; j++) { pa[j] = pk2(ac[j], ac[j+2]); pd[j] = pk2(dc[j], dc[j+2]); }
  u64 y0P = 0ull, y0Q = 0ull, y1P = 0ull, y1Q = 0ull;
  #pragma unroll
  for (int u = 0; u < 8; u++) {
    u64 a1 = pa[7-u], a2 = pa[8-u], d1 = pd[7-u], d2 = pd[8-u];
    u64 re = cpair(RLB, 2*u), rh = cpair(RLB, 15-2*u);
    u64 ro = cpair(RLB, 2*u+1), rn = cpair(RLNB, 14-2*u);
    y0P = ffma2(a1, re, y0P); y0P = ffma2(d1, rh, y0P);
    y0Q = ffma2(a2, re, y0Q); y0Q = ffma2(d2, rh, y0Q);
    y1P = ffma2(a1, ro, y1P); y1P = ffma2(d1, rn, y1P);
    y1Q = ffma2(a2, ro, y1Q); y1Q = ffma2(d2, rn, y1Q);
  }
  float2 f;
  f = up2(y0P); y0[0] = f.x; y0[2] = f.y;
  f = up2(y0Q); y0[1] = f.x; y0[3] = f.y;
  f = up2(y1P); y1[0] = f.x; y1[2] = f.y;
  f = up2(y1Q); y1[1] = f.x; y1[3] = f.y;
}

__device__ float g_lo[(size_t)NM*NH*SW];
__device__ float g_hi[(size_t)NM*NH*SW];
__device__ float g_ll[(size_t)NM*SW*SW];   // subbands: layout [m][jh][w]
__device__ float g_lh[(size_t)NM*SW*SW];
__device__ float g_hl[(size_t)NM*SW*SW];
__device__ float g_hh[(size_t)NM*SW*SW];
__device__ float g_thr[NM];
__device__ unsigned g_hist0[NM*2048];
__device__ unsigned g_hist1[NM*2048];
__device__ unsigned g_ccnt[NM];
__device__ unsigned g_pref0[NM];
__device__ unsigned g_rank1[NM];
__device__ unsigned g_cand[(size_t)NM*CAP];

__device__ __forceinline__ int refl(int q, int n) {
  q = (q < 0) ? (-q - 1) : q;
  return (q >= n) ? (2*n - 1 - q) : q;
}
__device__ __forceinline__ float softf(float c, float t) {
  float a = fabsf(c) - t;
  return (a > 0.f) ? copysignf(a, c) : 0.f;
}
__device__ __forceinline__ void hadd(unsigned* h, unsigned bin) {
  unsigned mk = __match_any_sync(__activemask(), bin);
  int lane = threadIdx.x & 31;
  if ((__ffs(mk) - 1) == lane) atomicAdd(&h[bin], (unsigned)__popc(mk));
}

template<int NT, int K>
__device__ void select_bin(const unsigned* hist, unsigned rank,
                           unsigned* s_bin, unsigned* s_rem) {
  __shared__ unsigned wtot[NT/32];
  int tid = threadIdx.x, lane = tid & 31, wid = tid >> 5;
  unsigned tsum = 0;
  #pragma unroll
  for (int k = 0; k < K; k++) tsum += hist[tid*K + k];
  unsigned v = tsum;
  #pragma unroll
  for (int o = 1; o < 32; o <<= 1) {
    unsigned n = __shfl_up_sync(0xffffffffu, v, o);
    if (lane >= o) v += n;
  }
  if (lane == 31) wtot[wid] = v;
  __syncthreads();
  if (tid == 0) {
    unsigned s = 0;
    for (int w = 0; w < NT/32; w++) { unsigned t = wtot[w]; wtot[w] = s; s += t; }
  }
  __syncthreads();
  unsigned incl = v + wtot[wid];
  unsigned excl = incl - tsum;
  if (rank >= excl && rank < incl) {
    unsigned c = excl;
    #pragma unroll
    for (int k = 0; k < K; k++) {
      unsigned hb = hist[tid*K + k];
      if (rank < c + hb) { *s_bin = (unsigned)(tid*K + k); *s_rem = rank - c; break; }
      c += hb;
    }
  }
  __syncthreads();
}

// ---- tiny zero kernels (keep k_fwd_cols as 4th launch -> profiled) ---------
__global__ void k_zero_a() {
  int i = blockIdx.x*256 + threadIdx.x;
  if (i < NM*2048) g_hist0[i] = 0u;
  if (i < NM) g_ccnt[i] = 0u;
}
__global__ void k_zero_b() {
  int i = blockIdx.x*256 + threadIdx.x;
  if (i < NM*2048) g_hist1[i] = 0u;
}

// ---- A: row DWT (along W), 2 rows/block, 3 channels ------------------------
__global__ void __launch_bounds__(256) k_fwd_rows(const float* __restrict__ x) {
  __shared__ float s[2][1728];
  int h0 = blockIdx.x*2, b = blockIdx.y;
  const float4* row4 = (const float4*)(x + (size_t)(b*NH + h0)*NW*3);
  #pragma unroll
  for (int u = 0; u < 3; u++) {
    int i = u*256 + threadIdx.x;
    float4 v = row4[i];
    int rr = i / 384, lin = 4*(i - 384*rr);
    #pragma unroll
    for (int e = 0; e < 4; e++) {
      int l = lin + e, c = l % 3, w = l / 3;
      s[rr][c*576 + w + (w >> 3)] = (&v.x)[e];
    }
  }
  __syncthreads();
  for (int t = threadIdx.x; t < 396; t += 256) {
    int rr = t / 198, t2 = t - 198*rr;
    int c = t2 / 66, g = t2 - 66*c;
    const float* sc = s[rr] + c*576;
    float samp[22];
    int q0 = 8*g - 14;
    #pragma unroll
    for (int k = 0; k < 22; k++) { int q = refl(q0 + k, NW); samp[k] = sc[q + (q >> 3)]; }
    float a[4], d[4];
    fwd8(samp, a, d);
    size_t base = ((size_t)(b*3 + c)*NH + h0 + rr)*SW + 4*g;
    *(float4*)(g_lo + base) = make_float4(a[0],a[1],a[2],a[3]);
    *(float4*)(g_hi + base) = make_float4(d[0],d[1],d[2],d[3]);
  }
}

// ---- B: column DWT split-H -> subbands [m][jh][w] + fused pass-0 hist ------
// smem tile row-major [row][w] stride 36; float4 global loads, 16B smem stores
__global__ void __launch_bounds__(256) k_fwd_cols() {
  __shared__ float s2[150*36];
  __shared__ unsigned hist[2048];
  int bx = blockIdx.x, wt = bx % 9, jc = bx / 9;
  int m = blockIdx.y, z = blockIdx.z;
  int w0 = wt*32, g0 = 17*jc;
  int ge = min(g0 + 16, 65);
  int lo_q = 8*g0 - 14;
  int nrows = 8*(ge - g0) + 22;
  const float* in = (z ? g_hi : g_lo) + (size_t)m*NH*SW;
  float* outA = (z ? g_hl : g_ll) + (size_t)m*SW*SW;
  float* outD = (z ? g_hh : g_lh) + (size_t)m*SW*SW;
  for (int i = threadIdx.x; i < 2048; i += 256) hist[i] = 0u;
  int nvec = nrows*8;
  #pragma unroll
  for (int u = 0; u < 5; u++) {
    int idx = u*256 + threadIdx.x;
    if (idx < nvec) {
      int wl4 = idx & 7, rr = idx >> 3;
      int wbase = w0 + 4*wl4;
      if (wbase < SW) {           // skip OOB float4s on last tile
        int q = refl(lo_q + rr, NH);
        float4 v = *(const float4*)(in + (size_t)q*SW + wbase);
        float* dst = s2 + rr*36 + 4*wl4;
        dst[0] = (wbase + 0 < NCo) ? v.x : 0.f;
        dst[1] = (wbase + 1 < NCo) ? v.y : 0.f;
        dst[2] = (wbase + 2 < NCo) ? v.z : 0.f;
        dst[3] = (wbase + 3 < NCo) ? v.w : 0.f;
      }
    }
  }
  __syncthreads();
  int lane = threadIdx.x & 31, warp = threadIdx.x >> 5;
  int w = w0 + lane;
  const float* col = s2 + lane;
  for (int g = g0 + warp; g <= ge; g += 8) {
    int off = 8*(g - g0);
    float samp[22];
    #pragma unroll
    for (int k = 0; k < 22; k++) samp[k] = col[(off + k)*36];
    float a[4], d[4];
    fwd8(samp, a, d);
    if (g == 65) { a[3] = 0.f; d[3] = 0.f; } // jh==263 pad row
    if (w < SW) {
      #pragma unroll
      for (int r = 0; r < 4; r++) {
        int jh = 4*g + r;
        outA[(size_t)jh*SW + w] = a[r];
        outD[(size_t)jh*SW + w] = d[r];
        hadd(hist, __float_as_uint(fabsf(d[r])) >> 21);
        if (z) hadd(hist, __float_as_uint(fabsf(a[r])) >> 21);
      }
    }
  }
  __syncthreads();
  for (int i = threadIdx.x; i < 2048; i += 256)
    if (hist[i]) atomicAdd(&g_hist0[m*2048 + i], hist[i]);
}

// ---- M2: redundant pass-0 select + refine hist + compact matching keys -----
__global__ void __launch_bounds__(256) k_pass1() {
  __shared__ unsigned hist[2048];
  __shared__ unsigned s_bin, s_rem;
  int cx = blockIdx.x, m = blockIdx.y, band = blockIdx.z;
  select_bin<256, 8>(g_hist0 + m*2048, RANKSEL, &s_bin, &s_rem);
  unsigned pref0 = s_bin;
  if (cx == 0 && band == 0 && threadIdx.x == 0) {
    g_pref0[m] = s_bin; g_rank1[m] = s_rem;
  }
  const float* bp = (band == 0 ? g_lh : (band == 1 ? g_hl : g_hh)) + (size_t)m*SW*SW;
  const float4* p = (const float4*)bp;
  for (int i = threadIdx.x; i < 2048; i += 256) hist[i] = 0u;
  __syncthreads();
  int lo = cx*2178, hi = lo + 2178;
  int lane = threadIdx.x & 31;
  for (int base = lo; base < hi; base += 256) {
    int i = base + threadIdx.x;
    float4 v = make_float4(0.f, 0.f, 0.f, 0.f);
    if (i < hi) v = p[i];
    #pragma unroll
    for (int e = 0; e < 4; e++) {
      unsigned key = __float_as_uint(fabsf((&v.x)[e]));
      bool ok = (i < hi) && ((key >> 21) == pref0);
      unsigned mk = __ballot_sync(0xffffffffu, ok);
      if (mk) {
        int leader = __ffs(mk) - 1;
        unsigned basec = 0;
        if (lane == leader) basec = atomicAdd(&g_ccnt[m], (unsigned)__popc(mk));
        basec = __shfl_sync(0xffffffffu, basec, leader);
        if (ok) {
          atomicAdd(&hist[(key >> 10) & 2047u], 1u);
          g_cand[(size_t)m*CAP + basec + __popc(mk & ((1u << lane) - 1u))] = key;
        }
      }
    }
  }
  __syncthreads();
  for (int i = threadIdx.x; i < 2048; i += 256)
    if (hist[i]) atomicAdd(&g_hist1[m*2048 + i], hist[i]);
}

// ---- M3: finish on candidates -> threshold ---------------------------------
__global__ void __launch_bounds__(512) k_final() {
  int m = blockIdx.x;
  __shared__ unsigned sh[2048];
  __shared__ unsigned s_bin, s_rem;
  for (int i = threadIdx.x; i < 2048; i += 512) sh[i] = g_hist1[m*2048 + i];
  __syncthreads();
  select_bin<512, 4>(sh, g_rank1[m], &s_bin, &s_rem);
  unsigned pref01 = (g_pref0[m] << 11) | s_bin;
  unsigned r2 = s_rem;
  __syncthreads();
  for (int i = threadIdx.x; i < 1024; i += 512) sh[i] = 0u;
  __syncthreads();
  unsigned cnt = g_ccnt[m];
  const unsigned* cand = g_cand + (size_t)m*CAP;
  for (unsigned i = threadIdx.x; i < cnt; i += 512) {
    unsigned key = cand[i];
    if ((key >> 10) == pref01) atomicAdd(&sh[key & 1023u], 1u);
  }
  __syncthreads();
  select_bin<512, 2>(sh, r2, &s_bin, &s_rem);
  if (threadIdx.x == 0) {
    unsigned key = (pref01 << 10) | s_bin;
    double med = (double)__uint_as_float(key);
    g_thr[m] = (float)(med / 0.6745 * sqrt(2.0 * log(262144.0)));
  }
}

// ---- C: inverse column DWT (subbands [jh][w]), soft fused ------------------
// smem tiles row-major [p][w] stride 36; float4 global loads
__global__ void __launch_bounds__(256) k_inv_cols() {
  __shared__ float ca[71*36], cd[71*36];
  int bx = blockIdx.x, wt = bx % 9, jc = bx / 9;
  int m = blockIdx.y, z = blockIdx.z;
  int w0 = wt*32, gc0 = 16*jc, p_lo = 64*jc;
  const float* A = (z ? g_hl : g_ll) + (size_t)m*SW*SW;
  const float* D = (z ? g_hh : g_lh) + (size_t)m*SW*SW;
  float* out = (z ? g_hi : g_lo) + (size_t)m*NH*SW;
  float thr = g_thr[m];
  #pragma unroll
  for (int u = 0; u < 3; u++) {
    int idx = u*256 + threadIdx.x;
    if (idx < 568) {
      int wl4 = idx & 7, rr = idx >> 3;
      int wbase = w0 + 4*wl4;
      if (wbase < SW) {
        size_t off = (size_t)(p_lo + rr)*SW + wbase;
        float4 va = *(const float4*)(A + off);
        float4 vd = *(const float4*)(D + off);
        if (z) {
          va.x = softf(va.x, thr); va.y = softf(va.y, thr);
          va.z = softf(va.z, thr); va.w = softf(va.w, thr);
        }
        vd.x = softf(vd.x, thr); vd.y = softf(vd.y, thr);
        vd.z = softf(vd.z, thr); vd.w = softf(vd.w, thr);
        float* pa = ca + rr*36 + 4*wl4;
        float* pd = cd + rr*36 + 4*wl4;
        pa[0] = va.x; pa[1] = va.y; pa[2] = va.z; pa[3] = va.w;
        pd[0] = vd.x; pd[1] = vd.y; pd[2] = vd.z; pd[3] = vd.w;
      }
    }
  }
  __syncthreads();
  int lane = threadIdx.x & 31, warp = threadIdx.x >> 5;
  int w = w0 + lane;
  bool wok = (w < NCo);
  const float* cap = ca + lane;
  const float* cdp = cd + lane;
  for (int gl = warp; gl < 16; gl += 8) {
    int gc = gc0 + gl, pr = 4*gl;
    float ac[11], dc[11];
    #pragma unroll
    for (int k = 0; k < 11; k++) { ac[k] = cap[(pr + k)*36]; dc[k] = cdp[(pr + k)*36]; }
    float y0[4], y1[4];
    inv8(ac, dc, y0, y1);
    if (wok) {
      #pragma unroll
      for (int r = 0; r < 4; r++) {
        int i0 = 8*gc + 2*r;
        out[(size_t)i0*SW + w]     = y0[r];
        out[(size_t)(i0+1)*SW + w] = y1[r];
      }
    }
  }
}

// ---- D: inverse row DWT + NHWC interleave, 2 rows/block --------------------
__global__ void __launch_bounds__(256) k_inv_rows(float* __restrict__ out) {
  __shared__ float ca[2][888], cd[2][888], rowbuf[2][1536];
  int h0 = blockIdx.x*2, b = blockIdx.y;
  #pragma unroll
  for (int u = 0; u < 2; u++) {
    int i = u*256 + threadIdx.x;
    if (i < 396) {
      int rr = i / 198, t2 = i - 198*rr;
      int c = t2 / 66, f = t2 - 66*c;
      const float4* rl4 = (const float4*)(g_lo + ((size_t)(b*3 + c)*NH + h0 + rr)*SW);
      const float4* rh4 = (const float4*)(g_hi + ((size_t)(b*3 + c)*NH + h0 + rr)*SW);
      float4 va = rl4[f], vd = rh4[f];
      int a0 = c*296 + 4*f + (f >> 1);
      #pragma unroll
      for (int e = 0; e < 4; e++) { ca[rr][a0 + e] = (&va.x)[e]; cd[rr][a0 + e] = (&vd.x)[e]; }
    }
  }
  __syncthreads();
  for (int t = threadIdx.x; t < 384; t += 256) {
    int rr = t / 192, rem = t - 192*rr;
    int c = rem >> 6, gc = rem & 63, p0 = 4*gc;
    float ac[11], dc[11];
    #pragma unroll
    for (int k = 0; k < 11; k++) {
      int p = p0 + k, a = c*296 + p + (p >> 3);
      ac[k] = ca[rr][a]; dc[k] = cd[rr][a];
    }
    float y0[4], y1[4];
    inv8(ac, dc, y0, y1);
    #pragma unroll
    for (int r = 0; r < 4; r++) {
      int o = 2*(p0 + r);
      rowbuf[rr][o*3 + c]       = y0[r];
      rowbuf[rr][(o + 1)*3 + c] = y1[r];
    }
  }
  __syncthreads();
  float4* orow = (float4*)(out + (size_t)(b*NH + h0)*NW*3);
  const float4* rb = (const float4*)rowbuf;
  #pragma unroll
  for (int u = 0; u < 3; u++) orow[u*256 + threadIdx.x] = rb[u*256 + threadIdx.x];
}

extern "C" void kernel_launch(void* const* d_in, const int* in_sizes, int n_in,
                              void* d_out, int out_size) {
  const float* x = (const float*)d_in[0];
  float* out = (float*)d_out;
  k_zero_a<<<(NM*2048 + 255)/256, 256>>>();
  k_zero_b<<<(NM*2048 + 255)/256, 256>>>();
  k_fwd_rows<<<dim3(NH/2, NB), 256>>>(x);
  k_fwd_cols<<<dim3(36, NM, 2), 256>>>();   // 4th launch -> ncu captures this
  k_pass1<<<dim3(8, NM, 3), 256>>>();
  k_final<<<NM, 512>>>();
  k_inv_cols<<<dim3(36, NM, 2), 256>>>();
  k_inv_rows<<<dim3(NH/2, NB), 256>>>(out);
}

// round 15
// speedup vs baseline: 1.0954x; 1.0274x over previous
#include <cuda_runtime.h>
#include <math.h>

#define NB 32
#define NH 512
#define NW 512
#define NM 96
#define NCo 263
#define SW 264
#define RANKSEL 105334u   // 0-based median rank incl. 1581 pad zeros per plane
#define CAP 207872

#define T0   0.05441584224308161f
#define T1   0.3128715909144659f
#define T2   0.6756307362980128f
#define T3   0.5853546836548691f
#define T4  -0.015829105256023893f
#define T5  -0.2840155429624281f
#define T6   0.00047248457399797254f
#define T7   0.128747426620186f
#define T8  -0.01736930100202211f
#define T9  -0.04408825393106472f
#define T10  0.013981027917015516f
#define T11  0.008746094047015655f
#define T12 -0.00487035299301066f
#define T13 -0.0003917403729959771f
#define T14  0.0006754494059985568f
#define T15 -0.00011747678400228192f

__constant__ __align__(8) float RLB[16][2] = {
 {T0,T0},{T1,T1},{T2,T2},{T3,T3},{T4,T4},{T5,T5},{T6,T6},{T7,T7},
 {T8,T8},{T9,T9},{T10,T10},{T11,T11},{T12,T12},{T13,T13},{T14,T14},{T15,T15}};
__constant__ __align__(8) float DHB[16][2] = {
 {T15,T15},{-T14,-T14},{T13,T13},{-T12,-T12},{T11,T11},{-T10,-T10},{T9,T9},{-T8,-T8},
 {T7,T7},{-T6,-T6},{T5,T5},{-T4,-T4},{T3,T3},{-T2,-T2},{T1,T1},{-T0,-T0}};
__constant__ __align__(8) float RLNB[16][2] = {
 {-T0,-T0},{-T1,-T1},{-T2,-T2},{-T3,-T3},{-T4,-T4},{-T5,-T5},{-T6,-T6},{-T7,-T7},
 {-T8,-T8},{-T9,-T9},{-T10,-T10},{-T11,-T11},{-T12,-T12},{-T13,-T13},{-T14,-T14},{-T15,-T15}};

typedef unsigned long long u64;
__device__ __forceinline__ u64 pk2(float lo, float hi) {
  u64 r; asm("mov.b64 %0, {%1, %2};" : "=l"(r) : "f"(lo), "f"(hi)); return r;
}
__device__ __forceinline__ u64 ffma2(u64 a, u64 b, u64 c) {
  u64 d; asm("fma.rn.f32x2 %0, %1, %2, %3;" : "=l"(d) : "l"(a), "l"(b), "l"(c)); return d;
}
__device__ __forceinline__ float2 up2(u64 v) {
  float2 f; asm("mov.b64 {%0, %1}, %2;" : "=f"(f.x), "=f"(f.y) : "l"(v)); return f;
}
__device__ __forceinline__ u64 cpair(const float (*tab)[2], int i) {
  return *(const u64*)(tab[i]);
}

__device__ __forceinline__ void fwd8(const float* samp, float* a, float* d) {
  u64 p[18];
  #pragma unroll
  for (int j = 0; j < 18; j++) p[j] = pk2(samp[j], samp[j+4]);
  u64 aP = 0ull, aQ = 0ull, dP = 0ull, dQ = 0ull;
  #pragma unroll
  for (int i = 0; i < 16; i++) {
    u64 rl = cpair(RLB, i), dh = cpair(DHB, i);
    aP = ffma2(rl, p[i],   aP);
    aQ = ffma2(rl, p[i+2], aQ);
    dP = ffma2(dh, p[i],   dP);
    dQ = ffma2(dh, p[i+2], dQ);
  }
  float2 f;
  f = up2(aP); a[0] = f.x; a[2] = f.y;
  f = up2(aQ); a[1] = f.x; a[3] = f.y;
  f = up2(dP); d[0] = f.x; d[2] = f.y;
  f = up2(dQ); d[1] = f.x; d[3] = f.y;
}

__device__ __forceinline__ void inv8(const float* ac, const float* dc,
                                     float* y0, float* y1) {
  u64 pa[9], pd[9];
  #pragma unroll
  for (int j = 0; j < 9; j++) { pa[j] = pk2(ac[j], ac[j+2]); pd[j] = pk2(dc[j], dc[j+2]); }
  u64 y0P = 0ull, y0Q = 0ull, y1P = 0ull, y1Q = 0ull;
  #pragma unroll
  for (int u = 0; u < 8; u++) {
    u64 a1 = pa[7-u], a2 = pa[8-u], d1 = pd[7-u], d2 = pd[8-u];
    u64 re = cpair(RLB, 2*u), rh = cpair(RLB, 15-2*u);
    u64 ro = cpair(RLB, 2*u+1), rn = cpair(RLNB, 14-2*u);
    y0P = ffma2(a1, re, y0P); y0P = ffma2(d1, rh, y0P);
    y0Q = ffma2(a2, re, y0Q); y0Q = ffma2(d2, rh, y0Q);
    y1P = ffma2(a1, ro, y1P); y1P = ffma2(d1, rn, y1P);
    y1Q = ffma2(a2, ro, y1Q); y1Q = ffma2(d2, rn, y1Q);
  }
  float2 f;
  f = up2(y0P); y0[0] = f.x; y0[2] = f.y;
  f = up2(y0Q); y0[1] = f.x; y0[3] = f.y;
  f = up2(y1P); y1[0] = f.x; y1[2] = f.y;
  f = up2(y1Q); y1[1] = f.x; y1[3] = f.y;
}

__device__ float g_lo[(size_t)NM*NH*SW];
__device__ float g_hi[(size_t)NM*NH*SW];
__device__ float g_ll[(size_t)NM*SW*SW];   // subbands: layout [m][jh][w]
__device__ float g_lh[(size_t)NM*SW*SW];
__device__ float g_hl[(size_t)NM*SW*SW];
__device__ float g_hh[(size_t)NM*SW*SW];
__device__ float g_thr[NM];
__device__ unsigned g_hist0[NM*2048];
__device__ unsigned g_hist1[NM*2048];
__device__ unsigned g_ccnt[NM];
__device__ unsigned g_pref0[NM];
__device__ unsigned g_rank1[NM];
__device__ unsigned g_cand[(size_t)NM*CAP];

__device__ __forceinline__ int refl(int q, int n) {
  q = (q < 0) ? (-q - 1) : q;
  return (q >= n) ? (2*n - 1 - q) : q;
}
__device__ __forceinline__ float softf(float c, float t) {
  float a = fabsf(c) - t;
  return (a > 0.f) ? copysignf(a, c) : 0.f;
}
__device__ __forceinline__ void hadd(unsigned* h, unsigned bin) {
  unsigned mk = __match_any_sync(__activemask(), bin);
  int lane = threadIdx.x & 31;
  if ((__ffs(mk) - 1) == lane) atomicAdd(&h[bin], (unsigned)__popc(mk));
}

template<int NT, int K>
__device__ void select_bin(const unsigned* hist, unsigned rank,
                           unsigned* s_bin, unsigned* s_rem) {
  __shared__ unsigned wtot[NT/32];
  int tid = threadIdx.x, lane = tid & 31, wid = tid >> 5;
  unsigned tsum = 0;
  #pragma unroll
  for (int k = 0; k < K; k++) tsum += hist[tid*K + k];
  unsigned v = tsum;
  #pragma unroll
  for (int o = 1; o < 32; o <<= 1) {
    unsigned n = __shfl_up_sync(0xffffffffu, v, o);
    if (lane >= o) v += n;
  }
  if (lane == 31) wtot[wid] = v;
  __syncthreads();
  if (tid == 0) {
    unsigned s = 0;
    for (int w = 0; w < NT/32; w++) { unsigned t = wtot[w]; wtot[w] = s; s += t; }
  }
  __syncthreads();
  unsigned incl = v + wtot[wid];
  unsigned excl = incl - tsum;
  if (rank >= excl && rank < incl) {
    unsigned c = excl;
    #pragma unroll
    for (int k = 0; k < K; k++) {
      unsigned hb = hist[tid*K + k];
      if (rank < c + hb) { *s_bin = (unsigned)(tid*K + k); *s_rem = rank - c; break; }
      c += hb;
    }
  }
  __syncthreads();
}

// ---- tiny zero kernels (keep k_fwd_cols as 4th launch -> profiled) ---------
__global__ void k_zero_a() {
  int i = blockIdx.x*256 + threadIdx.x;
  if (i < NM*2048) g_hist0[i] = 0u;
  if (i < NM) g_ccnt[i] = 0u;
}
__global__ void k_zero_b() {
  int i = blockIdx.x*256 + threadIdx.x;
  if (i < NM*2048) g_hist1[i] = 0u;
}

// ---- A: row DWT (along W), 2 rows/block, 3 channels ------------------------
__global__ void __launch_bounds__(256) k_fwd_rows(const float* __restrict__ x) {
  __shared__ float s[2][1728];
  int h0 = blockIdx.x*2, b = blockIdx.y;
  const float4* row4 = (const float4*)(x + (size_t)(b*NH + h0)*NW*3);
  #pragma unroll
  for (int u = 0; u < 3; u++) {
    int i = u*256 + threadIdx.x;
    float4 v = row4[i];
    int rr = i / 384, lin = 4*(i - 384*rr);
    #pragma unroll
    for (int e = 0; e < 4; e++) {
      int l = lin + e, c = l % 3, w = l / 3;
      s[rr][c*576 + w + (w >> 3)] = (&v.x)[e];
    }
  }
  __syncthreads();
  for (int t = threadIdx.x; t < 396; t += 256) {
    int rr = t / 198, t2 = t - 198*rr;
    int c = t2 / 66, g = t2 - 66*c;
    const float* sc = s[rr] + c*576;
    float samp[22];
    int q0 = 8*g - 14;
    #pragma unroll
    for (int k = 0; k < 22; k++) { int q = refl(q0 + k, NW); samp[k] = sc[q + (q >> 3)]; }
    float a[4], d[4];
    fwd8(samp, a, d);
    size_t base = ((size_t)(b*3 + c)*NH + h0 + rr)*SW + 4*g;
    *(float4*)(g_lo + base) = make_float4(a[0],a[1],a[2],a[3]);
    *(float4*)(g_hi + base) = make_float4(d[0],d[1],d[2],d[3]);
  }
}

// ---- B: column DWT, DIRECT global reads (no staging) + fused pass-0 hist ---
// taps at fixed row offsets k*SW from one base pointer -> 22 imm-offset LDGs,
// lane-contiguous (coalesced); redundant row re-reads hit L1.
__global__ void __launch_bounds__(256) k_fwd_cols() {
  __shared__ unsigned hist[2048];
  int bx = blockIdx.x, wt = bx % 9, jc = bx / 9;
  int m = blockIdx.y, z = blockIdx.z;
  int w0 = wt*32, g0 = 17*jc;
  int ge = min(g0 + 16, 65);
  const float* in = (z ? g_hi : g_lo) + (size_t)m*NH*SW;
  float* outA = (z ? g_hl : g_ll) + (size_t)m*SW*SW;
  float* outD = (z ? g_hh : g_lh) + (size_t)m*SW*SW;
  for (int i = threadIdx.x; i < 2048; i += 256) hist[i] = 0u;
  __syncthreads();
  int lane = threadIdx.x & 31, warp = threadIdx.x >> 5;
  int w = w0 + lane;
  bool wfull = (w0 + 31 < NCo);         // fast tile: all lanes valid
  bool win = (w < NCo);
  int wc = win ? w : (NCo - 1);         // clamped address for pad lanes
  for (int g = g0 + warp; g <= ge; g += 8) {
    int qg = 8*g - 14;
    float samp[22];
    if (qg >= 0 && qg + 21 < NH) {
      const float* bp = in + (size_t)qg*SW + wc;
      if (wfull) {
        #pragma unroll
        for (int k = 0; k < 22; k++) samp[k] = bp[k*SW];
      } else {
        #pragma unroll
        for (int k = 0; k < 22; k++) samp[k] = win ? bp[k*SW] : 0.f;
      }
    } else {
      #pragma unroll
      for (int k = 0; k < 22; k++) {
        int q = refl(qg + k, NH);
        samp[k] = win ? in[(size_t)q*SW + wc] : 0.f;
      }
    }
    float a[4], d[4];
    fwd8(samp, a, d);
    if (g == 65) { a[3] = 0.f; d[3] = 0.f; } // jh==263 pad row
    if (w < SW) {
      #pragma unroll
      for (int r = 0; r < 4; r++) {
        int jh = 4*g + r;
        outA[(size_t)jh*SW + w] = a[r];
        outD[(size_t)jh*SW + w] = d[r];
        hadd(hist, __float_as_uint(fabsf(d[r])) >> 21);
        if (z) hadd(hist, __float_as_uint(fabsf(a[r])) >> 21);
      }
    }
  }
  __syncthreads();
  for (int i = threadIdx.x; i < 2048; i += 256)
    if (hist[i]) atomicAdd(&g_hist0[m*2048 + i], hist[i]);
}

// ---- M2: redundant pass-0 select + refine hist + compact matching keys -----
__global__ void __launch_bounds__(256) k_pass1() {
  __shared__ unsigned hist[2048];
  __shared__ unsigned s_bin, s_rem;
  int cx = blockIdx.x, m = blockIdx.y, band = blockIdx.z;
  select_bin<256, 8>(g_hist0 + m*2048, RANKSEL, &s_bin, &s_rem);
  unsigned pref0 = s_bin;
  if (cx == 0 && band == 0 && threadIdx.x == 0) {
    g_pref0[m] = s_bin; g_rank1[m] = s_rem;
  }
  const float* bp = (band == 0 ? g_lh : (band == 1 ? g_hl : g_hh)) + (size_t)m*SW*SW;
  const float4* p = (const float4*)bp;
  for (int i = threadIdx.x; i < 2048; i += 256) hist[i] = 0u;
  __syncthreads();
  int lo = cx*2178, hi = lo + 2178;
  int lane = threadIdx.x & 31;
  for (int base = lo; base < hi; base += 256) {
    int i = base + threadIdx.x;
    float4 v = make_float4(0.f, 0.f, 0.f, 0.f);
    if (i < hi) v = p[i];
    #pragma unroll
    for (int e = 0; e < 4; e++) {
      unsigned key = __float_as_uint(fabsf((&v.x)[e]));
      bool ok = (i < hi) && ((key >> 21) == pref0);
      unsigned mk = __ballot_sync(0xffffffffu, ok);
      if (mk) {
        int leader = __ffs(mk) - 1;
        unsigned basec = 0;
        if (lane == leader) basec = atomicAdd(&g_ccnt[m], (unsigned)__popc(mk));
        basec = __shfl_sync(0xffffffffu, basec, leader);
        if (ok) {
          atomicAdd(&hist[(key >> 10) & 2047u], 1u);
          g_cand[(size_t)m*CAP + basec + __popc(mk & ((1u << lane) - 1u))] = key;
        }
      }
    }
  }
  __syncthreads();
  for (int i = threadIdx.x; i < 2048; i += 256)
    if (hist[i]) atomicAdd(&g_hist1[m*2048 + i], hist[i]);
}

// ---- M3: finish on candidates -> threshold ---------------------------------
__global__ void __launch_bounds__(512) k_final() {
  int m = blockIdx.x;
  __shared__ unsigned sh[2048];
  __shared__ unsigned s_bin, s_rem;
  for (int i = threadIdx.x; i < 2048; i += 512) sh[i] = g_hist1[m*2048 + i];
  __syncthreads();
  select_bin<512, 4>(sh, g_rank1[m], &s_bin, &s_rem);
  unsigned pref01 = (g_pref0[m] << 11) | s_bin;
  unsigned r2 = s_rem;
  __syncthreads();
  for (int i = threadIdx.x; i < 1024; i += 512) sh[i] = 0u;
  __syncthreads();
  unsigned cnt = g_ccnt[m];
  const unsigned* cand = g_cand + (size_t)m*CAP;
  for (unsigned i = threadIdx.x; i < cnt; i += 512) {
    unsigned key = cand[i];
    if ((key >> 10) == pref01) atomicAdd(&sh[key & 1023u], 1u);
  }
  __syncthreads();
  select_bin<512, 2>(sh, r2, &s_bin, &s_rem);
  if (threadIdx.x == 0) {
    unsigned key = (pref01 << 10) | s_bin;
    double med = (double)__uint_as_float(key);
    g_thr[m] = (float)(med / 0.6745 * sqrt(2.0 * log(262144.0)));
  }
}

// ---- C: inverse column DWT (subbands [jh][w]), soft fused, staged ----------
__global__ void __launch_bounds__(256) k_inv_cols() {
  __shared__ float ca[71*36], cd[71*36];
  int bx = blockIdx.x, wt = bx % 9, jc = bx / 9;
  int m = blockIdx.y, z = blockIdx.z;
  int w0 = wt*32, gc0 = 16*jc, p_lo = 64*jc;
  const float* A = (z ? g_hl : g_ll) + (size_t)m*SW*SW;
  const float* D = (z ? g_hh : g_lh) + (size_t)m*SW*SW;
  float* out = (z ? g_hi : g_lo) + (size_t)m*NH*SW;
  float thr = g_thr[m];
  #pragma unroll
  for (int u = 0; u < 3; u++) {
    int idx = u*256 + threadIdx.x;
    if (idx < 568) {
      int wl4 = idx & 7, rr = idx >> 3;
      int wbase = w0 + 4*wl4;
      if (wbase < SW) {
        size_t off = (size_t)(p_lo + rr)*SW + wbase;
        float4 va = *(const float4*)(A + off);
        float4 vd = *(const float4*)(D + off);
        if (z) {
          va.x = softf(va.x, thr); va.y = softf(va.y, thr);
          va.z = softf(va.z, thr); va.w = softf(va.w, thr);
        }
        vd.x = softf(vd.x, thr); vd.y = softf(vd.y, thr);
        vd.z = softf(vd.z, thr); vd.w = softf(vd.w, thr);
        float* pa = ca + rr*36 + 4*wl4;
        float* pd = cd + rr*36 + 4*wl4;
        pa[0] = va.x; pa[1] = va.y; pa[2] = va.z; pa[3] = va.w;
        pd[0] = vd.x; pd[1] = vd.y; pd[2] = vd.z; pd[3] = vd.w;
      }
    }
  }
  __syncthreads();
  int lane = threadIdx.x & 31, warp = threadIdx.x >> 5;
  int w = w0 + lane;
  bool wok = (w < NCo);
  const float* cap = ca + lane;
  const float* cdp = cd + lane;
  for (int gl = warp; gl < 16; gl += 8) {
    int gc = gc0 + gl, pr = 4*gl;
    float ac[11], dc[11];
    #pragma unroll
    for (int k = 0; k < 11; k++) { ac[k] = cap[(pr + k)*36]; dc[k] = cdp[(pr + k)*36]; }
    float y0[4], y1[4];
    inv8(ac, dc, y0, y1);
    if (wok) {
      #pragma unroll
      for (int r = 0; r < 4; r++) {
        int i0 = 8*gc + 2*r;
        out[(size_t)i0*SW + w]     = y0[r];
        out[(size_t)(i0+1)*SW + w] = y1[r];
      }
    }
  }
}

// ---- D: inverse row DWT + NHWC interleave, 2 rows/block --------------------
__global__ void __launch_bounds__(256) k_inv_rows(float* __restrict__ out) {
  __shared__ float ca[2][888], cd[2][888], rowbuf[2][1536];
  int h0 = blockIdx.x*2, b = blockIdx.y;
  #pragma unroll
  for (int u = 0; u < 2; u++) {
    int i = u*256 + threadIdx.x;
    if (i < 396) {
      int rr = i / 198, t2 = i - 198*rr;
      int c = t2 / 66, f = t2 - 66*c;
      const float4* rl4 = (const float4*)(g_lo + ((size_t)(b*3 + c)*NH + h0 + rr)*SW);
      const float4* rh4 = (const float4*)(g_hi + ((size_t)(b*3 + c)*NH + h0 + rr)*SW);
      float4 va = rl4[f], vd = rh4[f];
      int a0 = c*296 + 4*f + (f >> 1);
      #pragma unroll
      for (int e = 0; e < 4; e++) { ca[rr][a0 + e] = (&va.x)[e]; cd[rr][a0 + e] = (&vd.x)[e]; }
    }
  }
  __syncthreads();
  for (int t = threadIdx.x; t < 384; t += 256) {
    int rr = t / 192, rem = t - 192*rr;
    int c = rem >> 6, gc = rem & 63, p0 = 4*gc;
    float ac[11], dc[11];
    #pragma unroll
    for (int k = 0; k < 11; k++) {
      int p = p0 + k, a = c*296 + p + (p >> 3);
      ac[k] = ca[rr][a]; dc[k] = cd[rr][a];
    }
    float y0[4], y1[4];
    inv8(ac, dc, y0, y1);
    #pragma unroll
    for (int r = 0; r < 4; r++) {
      int o = 2*(p0 + r);
      rowbuf[rr][o*3 + c]       = y0[r];
      rowbuf[rr][(o + 1)*3 + c] = y1[r];
    }
  }
  __syncthreads();
  float4* orow = (float4*)(out + (size_t)(b*NH + h0)*NW*3);
  const float4* rb = (const float4*)rowbuf;
  #pragma unroll
  for (int u = 0; u < 3; u++) orow[u*256 + threadIdx.x] = rb[u*256 + threadIdx.x];
}

extern "C" void kernel_launch(void* const* d_in, const int* in_sizes, int n_in,
                              void* d_out, int out_size) {
  const float* x = (const float*)d_in[0];
  float* out = (float*)d_out;
  k_zero_a<<<(NM*2048 + 255)/256, 256>>>();
  k_zero_b<<<(NM*2048 + 255)/256, 256>>>();
  k_fwd_rows<<<dim3(NH/2, NB), 256>>>(x);
  k_fwd_cols<<<dim3(36, NM, 2), 256>>>();   // 4th launch -> ncu captures this
  k_pass1<<<dim3(8, NM, 3), 256>>>();
  k_final<<<NM, 512>>>();
  k_inv_cols<<<dim3(36, NM, 2), 256>>>();
  k_inv_rows<<<dim3(NH/2, NB), 256>>>(out);
}

// round 16
// speedup vs baseline: 1.2255x; 1.1188x over previous
#include <cuda_runtime.h>
#include <math.h>

#define NB 32
#define NH 512
#define NW 512
#define NM 96
#define NCo 263
#define SW 264
#define RANKSEL 105334u   // 0-based median rank incl. 1581 pad zeros per plane
#define CAP 207872

#define T0   0.05441584224308161f
#define T1   0.3128715909144659f
#define T2   0.6756307362980128f
#define T3   0.5853546836548691f
#define T4  -0.015829105256023893f
#define T5  -0.2840155429624281f
#define T6   0.00047248457399797254f
#define T7   0.128747426620186f
#define T8  -0.01736930100202211f
#define T9  -0.04408825393106472f
#define T10  0.013981027917015516f
#define T11  0.008746094047015655f
#define T12 -0.00487035299301066f
#define T13 -0.0003917403729959771f
#define T14  0.0006754494059985568f
#define T15 -0.00011747678400228192f

__constant__ __align__(8) float RLB[16][2] = {
 {T0,T0},{T1,T1},{T2,T2},{T3,T3},{T4,T4},{T5,T5},{T6,T6},{T7,T7},
 {T8,T8},{T9,T9},{T10,T10},{T11,T11},{T12,T12},{T13,T13},{T14,T14},{T15,T15}};
__constant__ __align__(8) float DHB[16][2] = {
 {T15,T15},{-T14,-T14},{T13,T13},{-T12,-T12},{T11,T11},{-T10,-T10},{T9,T9},{-T8,-T8},
 {T7,T7},{-T6,-T6},{T5,T5},{-T4,-T4},{T3,T3},{-T2,-T2},{T1,T1},{-T0,-T0}};
__constant__ __align__(8) float RLNB[16][2] = {
 {-T0,-T0},{-T1,-T1},{-T2,-T2},{-T3,-T3},{-T4,-T4},{-T5,-T5},{-T6,-T6},{-T7,-T7},
 {-T8,-T8},{-T9,-T9},{-T10,-T10},{-T11,-T11},{-T12,-T12},{-T13,-T13},{-T14,-T14},{-T15,-T15}};

typedef unsigned long long u64;
__device__ __forceinline__ u64 pk2(float lo, float hi) {
  u64 r; asm("mov.b64 %0, {%1, %2};" : "=l"(r) : "f"(lo), "f"(hi)); return r;
}
__device__ __forceinline__ u64 ffma2(u64 a, u64 b, u64 c) {
  u64 d; asm("fma.rn.f32x2 %0, %1, %2, %3;" : "=l"(d) : "l"(a), "l"(b), "l"(c)); return d;
}
__device__ __forceinline__ float2 up2(u64 v) {
  float2 f; asm("mov.b64 {%0, %1}, %2;" : "=f"(f.x), "=f"(f.y) : "l"(v)); return f;
}
__device__ __forceinline__ u64 cpair(const float (*tab)[2], int i) {
  return *(const u64*)(tab[i]);
}

__device__ __forceinline__ void fwd8(const float* samp, float* a, float* d) {
  u64 p[18];
  #pragma unroll
  for (int j = 0; j < 18; j++) p[j] = pk2(samp[j], samp[j+4]);
  u64 aP = 0ull, aQ = 0ull, dP = 0ull, dQ = 0ull;
  #pragma unroll
  for (int i = 0; i < 16; i++) {
    u64 rl = cpair(RLB, i), dh = cpair(DHB, i);
    aP = ffma2(rl, p[i],   aP);
    aQ = ffma2(rl, p[i+2], aQ);
    dP = ffma2(dh, p[i],   dP);
    dQ = ffma2(dh, p[i+2], dQ);
  }
  float2 f;
  f = up2(aP); a[0] = f.x; a[2] = f.y;
  f = up2(aQ); a[1] = f.x; a[3] = f.y;
  f = up2(dP); d[0] = f.x; d[2] = f.y;
  f = up2(dQ); d[1] = f.x; d[3] = f.y;
}

__device__ __forceinline__ void inv8(const float* ac, const float* dc,
                                     float* y0, float* y1) {
  u64 pa[9], pd[9];
  #pragma unroll
  for (int j = 0; j < 9; j++) { pa[j] = pk2(ac[j], ac[j+2]); pd[j] = pk2(dc[j], dc[j+2]); }
  u64 y0P = 0ull, y0Q = 0ull, y1P = 0ull, y1Q = 0ull;
  #pragma unroll
  for (int u = 0; u < 8; u++) {
    u64 a1 = pa[7-u], a2 = pa[8-u], d1 = pd[7-u], d2 = pd[8-u];
    u64 re = cpair(RLB, 2*u), rh = cpair(RLB, 15-2*u);
    u64 ro = cpair(RLB, 2*u+1), rn = cpair(RLNB, 14-2*u);
    y0P = ffma2(a1, re, y0P); y0P = ffma2(d1, rh, y0P);
    y0Q = ffma2(a2, re, y0Q); y0Q = ffma2(d2, rh, y0Q);
    y1P = ffma2(a1, ro, y1P); y1P = ffma2(d1, rn, y1P);
    y1Q = ffma2(a2, ro, y1Q); y1Q = ffma2(d2, rn, y1Q);
  }
  float2 f;
  f = up2(y0P); y0[0] = f.x; y0[2] = f.y;
  f = up2(y0Q); y0[1] = f.x; y0[3] = f.y;
  f = up2(y1P); y1[0] = f.x; y1[2] = f.y;
  f = up2(y1Q); y1[1] = f.x; y1[3] = f.y;
}

__device__ float g_lo[(size_t)NM*NH*SW];
__device__ float g_hi[(size_t)NM*NH*SW];
__device__ float g_ll[(size_t)NM*SW*SW];   // subbands: layout [m][jh][w]
__device__ float g_lh[(size_t)NM*SW*SW];
__device__ float g_hl[(size_t)NM*SW*SW];
__device__ float g_hh[(size_t)NM*SW*SW];
__device__ float g_thr[NM];
__device__ unsigned g_hist0[NM*2048];
__device__ unsigned g_hist1[NM*2048];
__device__ unsigned g_ccnt[NM];
__device__ unsigned g_pref0[NM];
__device__ unsigned g_rank1[NM];
__device__ unsigned g_cand[(size_t)NM*CAP];

__device__ __forceinline__ int refl(int q, int n) {
  q = (q < 0) ? (-q - 1) : q;
  return (q >= n) ? (2*n - 1 - q) : q;
}
__device__ __forceinline__ float softf(float c, float t) {
  float a = fabsf(c) - t;
  return (a > 0.f) ? copysignf(a, c) : 0.f;
}

template<int NT, int K>
__device__ void select_bin(const unsigned* hist, unsigned rank,
                           unsigned* s_bin, unsigned* s_rem) {
  __shared__ unsigned wtot[NT/32];
  int tid = threadIdx.x, lane = tid & 31, wid = tid >> 5;
  unsigned tsum = 0;
  #pragma unroll
  for (int k = 0; k < K; k++) tsum += hist[tid*K + k];
  unsigned v = tsum;
  #pragma unroll
  for (int o = 1; o < 32; o <<= 1) {
    unsigned n = __shfl_up_sync(0xffffffffu, v, o);
    if (lane >= o) v += n;
  }
  if (lane == 31) wtot[wid] = v;
  __syncthreads();
  if (tid == 0) {
    unsigned s = 0;
    for (int w = 0; w < NT/32; w++) { unsigned t = wtot[w]; wtot[w] = s; s += t; }
  }
  __syncthreads();
  unsigned incl = v + wtot[wid];
  unsigned excl = incl - tsum;
  if (rank >= excl && rank < incl) {
    unsigned c = excl;
    #pragma unroll
    for (int k = 0; k < K; k++) {
      unsigned hb = hist[tid*K + k];
      if (rank < c + hb) { *s_bin = (unsigned)(tid*K + k); *s_rem = rank - c; break; }
      c += hb;
    }
  }
  __syncthreads();
}

// ---- three tiny zero kernels (k_fwd_rows becomes 4th launch -> profiled) ---
__global__ void k_zero_a() {
  int i = blockIdx.x*256 + threadIdx.x;
  if (i < NM*2048) g_hist0[i] = 0u;
}
__global__ void k_zero_b() {
  int i = blockIdx.x*256 + threadIdx.x;
  if (i < NM*2048) g_hist1[i] = 0u;
}
__global__ void k_zero_c() {
  int i = threadIdx.x;
  if (i < NM) g_ccnt[i] = 0u;
}

// ---- A: row DWT (along W), 2 rows/block, 3 channels ------------------------
__global__ void __launch_bounds__(256) k_fwd_rows(const float* __restrict__ x) {
  __shared__ float s[2][1728];
  int h0 = blockIdx.x*2, b = blockIdx.y;
  const float4* row4 = (const float4*)(x + (size_t)(b*NH + h0)*NW*3);
  #pragma unroll
  for (int u = 0; u < 3; u++) {
    int i = u*256 + threadIdx.x;
    float4 v = row4[i];
    int rr = i / 384, lin = 4*(i - 384*rr);
    #pragma unroll
    for (int e = 0; e < 4; e++) {
      int l = lin + e, c = l % 3, w = l / 3;
      s[rr][c*576 + w + (w >> 3)] = (&v.x)[e];
    }
  }
  __syncthreads();
  for (int t = threadIdx.x; t < 396; t += 256) {
    int rr = t / 198, t2 = t - 198*rr;
    int c = t2 / 66, g = t2 - 66*c;
    const float* sc = s[rr] + c*576;
    float samp[22];
    int q0 = 8*g - 14;
    #pragma unroll
    for (int k = 0; k < 22; k++) { int q = refl(q0 + k, NW); samp[k] = sc[q + (q >> 3)]; }
    float a[4], d[4];
    fwd8(samp, a, d);
    size_t base = ((size_t)(b*3 + c)*NH + h0 + rr)*SW + 4*g;
    *(float4*)(g_lo + base) = make_float4(a[0],a[1],a[2],a[3]);
    *(float4*)(g_hi + base) = make_float4(d[0],d[1],d[2],d[3]);
  }
}

// ---- B: column DWT, direct global reads + fused pass-0 hist (plain atomics)-
__global__ void __launch_bounds__(256) k_fwd_cols() {
  __shared__ unsigned hist[2048];
  int bx = blockIdx.x, wt = bx % 9, jc = bx / 9;
  int m = blockIdx.y, z = blockIdx.z;
  int w0 = wt*32, g0 = 17*jc;
  int ge = min(g0 + 16, 65);
  const float* in = (z ? g_hi : g_lo) + (size_t)m*NH*SW;
  float* outA = (z ? g_hl : g_ll) + (size_t)m*SW*SW;
  float* outD = (z ? g_hh : g_lh) + (size_t)m*SW*SW;
  for (int i = threadIdx.x; i < 2048; i += 256) hist[i] = 0u;
  __syncthreads();
  int lane = threadIdx.x & 31, warp = threadIdx.x >> 5;
  int w = w0 + lane;
  bool wfull = (w0 + 31 < NCo);
  bool win = (w < NCo);
  int wc = win ? w : (NCo - 1);
  for (int g = g0 + warp; g <= ge; g += 8) {
    int qg = 8*g - 14;
    float samp[22];
    if (qg >= 0 && qg + 21 < NH) {
      const float* bp = in + (size_t)qg*SW + wc;
      if (wfull) {
        #pragma unroll
        for (int k = 0; k < 22; k++) samp[k] = bp[k*SW];
      } else {
        #pragma unroll
        for (int k = 0; k < 22; k++) samp[k] = win ? bp[k*SW] : 0.f;
      }
    } else {
      #pragma unroll
      for (int k = 0; k < 22; k++) {
        int q = refl(qg + k, NH);
        samp[k] = win ? in[(size_t)q*SW + wc] : 0.f;
      }
    }
    float a[4], d[4];
    fwd8(samp, a, d);
    if (g == 65) { a[3] = 0.f; d[3] = 0.f; } // jh==263 pad row
    if (w < SW) {
      #pragma unroll
      for (int r = 0; r < 4; r++) {
        int jh = 4*g + r;
        outA[(size_t)jh*SW + w] = a[r];
        outD[(size_t)jh*SW + w] = d[r];
        atomicAdd(&hist[__float_as_uint(fabsf(d[r])) >> 21], 1u);
        if (z) atomicAdd(&hist[__float_as_uint(fabsf(a[r])) >> 21], 1u);
      }
    }
  }
  __syncthreads();
  for (int i = threadIdx.x; i < 2048; i += 256)
    if (hist[i]) atomicAdd(&g_hist0[m*2048 + i], hist[i]);
}

// ---- M2: pass-0 select + refine hist + compact keys (predicated direct) ----
__global__ void __launch_bounds__(256) k_pass1() {
  __shared__ unsigned hist[2048];
  __shared__ unsigned s_bin, s_rem;
  int cx = blockIdx.x, m = blockIdx.y, band = blockIdx.z;
  select_bin<256, 8>(g_hist0 + m*2048, RANKSEL, &s_bin, &s_rem);
  unsigned pref0 = s_bin;
  if (cx == 0 && band == 0 && threadIdx.x == 0) {
    g_pref0[m] = s_bin; g_rank1[m] = s_rem;
  }
  const float* bp = (band == 0 ? g_lh : (band == 1 ? g_hl : g_hh)) + (size_t)m*SW*SW;
  const float4* p = (const float4*)bp;
  for (int i = threadIdx.x; i < 2048; i += 256) hist[i] = 0u;
  __syncthreads();
  int lo = cx*2178, hi = lo + 2178;
  unsigned* candm = g_cand + (size_t)m*CAP;
  for (int base = lo; base < hi; base += 256) {
    int i = base + threadIdx.x;
    if (i < hi) {
      float4 v = p[i];
      #pragma unroll
      for (int e = 0; e < 4; e++) {
        unsigned key = __float_as_uint(fabsf((&v.x)[e]));
        if ((key >> 21) == pref0) {
          unsigned pos = atomicAdd(&g_ccnt[m], 1u);
          candm[pos] = key;
          atomicAdd(&hist[(key >> 10) & 2047u], 1u);
        }
      }
    }
  }
  __syncthreads();
  for (int i = threadIdx.x; i < 2048; i += 256)
    if (hist[i]) atomicAdd(&g_hist1[m*2048 + i], hist[i]);
}

// ---- M3: finish on candidates -> threshold ---------------------------------
__global__ void __launch_bounds__(512) k_final() {
  int m = blockIdx.x;
  __shared__ unsigned sh[2048];
  __shared__ unsigned s_bin, s_rem;
  for (int i = threadIdx.x; i < 2048; i += 512) sh[i] = g_hist1[m*2048 + i];
  __syncthreads();
  select_bin<512, 4>(sh, g_rank1[m], &s_bin, &s_rem);
  unsigned pref01 = (g_pref0[m] << 11) | s_bin;
  unsigned r2 = s_rem;
  __syncthreads();
  for (int i = threadIdx.x; i < 1024; i += 512) sh[i] = 0u;
  __syncthreads();
  unsigned cnt = g_ccnt[m];
  const unsigned* cand = g_cand + (size_t)m*CAP;
  for (unsigned i = threadIdx.x; i < cnt; i += 512) {
    unsigned key = cand[i];
    if ((key >> 10) == pref01) atomicAdd(&sh[key & 1023u], 1u);
  }
  __syncthreads();
  select_bin<512, 2>(sh, r2, &s_bin, &s_rem);
  if (threadIdx.x == 0) {
    unsigned key = (pref01 << 10) | s_bin;
    double med = (double)__uint_as_float(key);
    g_thr[m] = (float)(med / 0.6745 * sqrt(2.0 * log(262144.0)));
  }
}

// ---- C: inverse column DWT (subbands [jh][w]), soft fused, staged ----------
__global__ void __launch_bounds__(256) k_inv_cols() {
  __shared__ float ca[71*36], cd[71*36];
  int bx = blockIdx.x, wt = bx % 9, jc = bx / 9;
  int m = blockIdx.y, z = blockIdx.z;
  int w0 = wt*32, gc0 = 16*jc, p_lo = 64*jc;
  const float* A = (z ? g_hl : g_ll) + (size_t)m*SW*SW;
  const float* D = (z ? g_hh : g_lh) + (size_t)m*SW*SW;
  float* out = (z ? g_hi : g_lo) + (size_t)m*NH*SW;
  float thr = g_thr[m];
  #pragma unroll
  for (int u = 0; u < 3; u++) {
    int idx = u*256 + threadIdx.x;
    if (idx < 568) {
      int wl4 = idx & 7, rr = idx >> 3;
      int wbase = w0 + 4*wl4;
      if (wbase < SW) {
        size_t off = (size_t)(p_lo + rr)*SW + wbase;
        float4 va = *(const float4*)(A + off);
        float4 vd = *(const float4*)(D + off);
        if (z) {
          va.x = softf(va.x, thr); va.y = softf(va.y, thr);
          va.z = softf(va.z, thr); va.w = softf(va.w, thr);
        }
        vd.x = softf(vd.x, thr); vd.y = softf(vd.y, thr);
        vd.z = softf(vd.z, thr); vd.w = softf(vd.w, thr);
        float* pa = ca + rr*36 + 4*wl4;
        float* pd = cd + rr*36 + 4*wl4;
        pa[0] = va.x; pa[1] = va.y; pa[2] = va.z; pa[3] = va.w;
        pd[0] = vd.x; pd[1] = vd.y; pd[2] = vd.z; pd[3] = vd.w;
      }
    }
  }
  __syncthreads();
  int lane = threadIdx.x & 31, warp = threadIdx.x >> 5;
  int w = w0 + lane;
  bool wok = (w < NCo);
  const float* cap = ca + lane;
  const float* cdp = cd + lane;
  for (int gl = warp; gl < 16; gl += 8) {
    int gc = gc0 + gl, pr = 4*gl;
    float ac[11], dc[11];
    #pragma unroll
    for (int k = 0; k < 11; k++) { ac[k] = cap[(pr + k)*36]; dc[k] = cdp[(pr + k)*36]; }
    float y0[4], y1[4];
    inv8(ac, dc, y0, y1);
    if (wok) {
      #pragma unroll
      for (int r = 0; r < 4; r++) {
        int i0 = 8*gc + 2*r;
        out[(size_t)i0*SW + w]     = y0[r];
        out[(size_t)(i0+1)*SW + w] = y1[r];
      }
    }
  }
}

// ---- D: inverse row DWT + NHWC interleave, 2 rows/block --------------------
__global__ void __launch_bounds__(256) k_inv_rows(float* __restrict__ out) {
  __shared__ float ca[2][888], cd[2][888], rowbuf[2][1536];
  int h0 = blockIdx.x*2, b = blockIdx.y;
  #pragma unroll
  for (int u = 0; u < 2; u++) {
    int i = u*256 + threadIdx.x;
    if (i < 396) {
      int rr = i / 198, t2 = i - 198*rr;
      int c = t2 / 66, f = t2 - 66*c;
      const float4* rl4 = (const float4*)(g_lo + ((size_t)(b*3 + c)*NH + h0 + rr)*SW);
      const float4* rh4 = (const float4*)(g_hi + ((size_t)(b*3 + c)*NH + h0 + rr)*SW);
      float4 va = rl4[f], vd = rh4[f];
      int a0 = c*296 + 4*f + (f >> 1);
      #pragma unroll
      for (int e = 0; e < 4; e++) { ca[rr][a0 + e] = (&va.x)[e]; cd[rr][a0 + e] = (&vd.x)[e]; }
    }
  }
  __syncthreads();
  for (int t = threadIdx.x; t < 384; t += 256) {
    int rr = t / 192, rem = t - 192*rr;
    int c = rem >> 6, gc = rem & 63, p0 = 4*gc;
    float ac[11], dc[11];
    #pragma unroll
    for (int k = 0; k < 11; k++) {
      int p = p0 + k, a = c*296 + p + (p >> 3);
      ac[k] = ca[rr][a]; dc[k] = cd[rr][a];
    }
    float y0[4], y1[4];
    inv8(ac, dc, y0, y1);
    #pragma unroll
    for (int r = 0; r < 4; r++) {
      int o = 2*(p0 + r);
      rowbuf[rr][o*3 + c]       = y0[r];
      rowbuf[rr][(o + 1)*3 + c] = y1[r];
    }
  }
  __syncthreads();
  float4* orow = (float4*)(out + (size_t)(b*NH + h0)*NW*3);
  const float4* rb = (const float4*)rowbuf;
  #pragma unroll
  for (int u = 0; u < 3; u++) orow[u*256 + threadIdx.x] = rb[u*256 + threadIdx.x];
}

extern "C" void kernel_launch(void* const* d_in, const int* in_sizes, int n_in,
                              void* d_out, int out_size) {
  const float* x = (const float*)d_in[0];
  float* out = (float*)d_out;
  k_zero_a<<<(NM*2048 + 255)/256, 256>>>();
  k_zero_b<<<(NM*2048 + 255)/256, 256>>>();
  k_zero_c<<<1, 256>>>();
  k_fwd_rows<<<dim3(NH/2, NB), 256>>>(x);   // 4th launch -> ncu captures this
  k_fwd_cols<<<dim3(36, NM, 2), 256>>>();
  k_pass1<<<dim3(8, NM, 3), 256>>>();
  k_final<<<NM, 512>>>();
  k_inv_cols<<<dim3(36, NM, 2), 256>>>();
  k_inv_rows<<<dim3(NH/2, NB), 256>>>(out);
}